// round 3
// baseline (speedup 1.0000x reference)
#include <cuda_runtime.h>
#include <math.h>

// Problem constants
#define BB 2
#define VV 180
#define RR 32
#define CC 512
#define NPIX 512
#define NROWS (BB*VV*RR)        // 11520
#define PADL 107
#define NPADE 724               // padded dup entries per row (covers floor(t)+PADL in [0,723])
#define YT 16
#define NSLAB (NPIX/YT)         // 32
#define PI_D 3.14159265358979323846

// ---------------- device globals (scratch; no runtime allocation allowed) ----------------
__device__ __align__(16) float  g_h[512];                    // ramp conv kernel
__device__ __align__(16) float2 g_cs[VV];                    // (cos, sin) per angle
__device__ __align__(16) float4 g_fp4[(size_t)NROWS * (NPADE/2)]; // padded dup filtered rows, ~67MB

// ---------------- setup: h[j] = (1/512) sum_m ramp[m] cos(2 pi m j / 512); cs table -----
__global__ void setup_kernel() {
    __shared__ double part[128];
    int tid = threadIdx.x;
    if (blockIdx.x == 512) {
        // angle table (VV=180 > 128 threads -> strided loop, NOT a single guard)
        for (int v = tid; v < VV; v += 128) {
            double th = PI_D * (double)v / (double)VV;
            g_cs[v] = make_float2((float)cos(th), (float)sin(th));
        }
        return;
    }
    int j = blockIdx.x;  // 0..511
    double s = 0.0;
    for (int m = tid; m < 512; m += 128) {
        double f = (m < 256) ? (double)m / 512.0 : (double)(m - 512) / 512.0;
        s += 2.0 * fabs(f) * cos(2.0 * PI_D * (double)m * (double)j / 512.0);
    }
    part[tid] = s;
    __syncthreads();
    for (int o = 64; o > 0; o >>= 1) {
        if (tid < o) part[tid] += part[tid + o];
        __syncthreads();
    }
    if (tid == 0) g_h[j] = (float)(part[0] / 512.0);
}

// ---------------- filter: circular conv + pad/dup write --------------------------------
// One block per sinogram row (11520 blocks), 128 threads, 4 consecutive outputs per thread.
__global__ void __launch_bounds__(128) filter_kernel(const float* __restrict__ sino) {
    __shared__ __align__(16) float srow2[1024];  // row duplicated (mod-512 window loads)
    __shared__ __align__(16) float sh[512];      // conv kernel
    __shared__ __align__(16) float sF[512];      // filtered output

    int row = blockIdx.x;
    int tid = threadIdx.x;

    const float4* rp = (const float4*)(sino + (size_t)row * CC);
    float4 rv4 = rp[tid];                               // 128 x float4 = 512 floats
    ((float4*)srow2)[tid]        = rv4;
    ((float4*)srow2)[tid + 128]  = rv4;                 // duplicate
    ((float4*)sh)[tid] = ((const float4*)g_h)[tid];
    __syncthreads();

    int c0 = tid * 4;
    float a0 = 0.f, a1 = 0.f, a2 = 0.f, a3 = 0.f;

    // F[c] = sum_d h[d] * row[(c-d) mod 512]
    #pragma unroll 4
    for (int d0 = 0; d0 < 512; d0 += 4) {
        float4 hv = *(const float4*)&sh[d0];            // broadcast across warp
        int base = c0 - d0 + 508;                       // 4-aligned, in [0,1016]
        float4 ra = *(const float4*)&srow2[base];       // offsets m=0..3 (rel idx c0-d0+508+m)
        float4 rb = *(const float4*)&srow2[base + 4];   // offsets m=4..7
        // acc_i += hv[j] * reg[i - j + 4]
        a0 = fmaf(hv.x, rb.x, a0); a0 = fmaf(hv.y, ra.w, a0); a0 = fmaf(hv.z, ra.z, a0); a0 = fmaf(hv.w, ra.y, a0);
        a1 = fmaf(hv.x, rb.y, a1); a1 = fmaf(hv.y, rb.x, a1); a1 = fmaf(hv.z, ra.w, a1); a1 = fmaf(hv.w, ra.z, a1);
        a2 = fmaf(hv.x, rb.z, a2); a2 = fmaf(hv.y, rb.y, a2); a2 = fmaf(hv.z, rb.x, a2); a2 = fmaf(hv.w, ra.w, a2);
        a3 = fmaf(hv.x, rb.w, a3); a3 = fmaf(hv.y, rb.z, a3); a3 = fmaf(hv.z, rb.y, a3); a3 = fmaf(hv.w, rb.x, a3);
    }
    *(float4*)&sF[c0] = make_float4(a0, a1, a2, a3);
    __syncthreads();

    // pad/dup: fp[j] = (F[clamp(j-107)], F[clamp(j-106)])
    float2* dst = ((float2*)g_fp4) + (size_t)row * NPADE;
    for (int j = tid; j < NPADE; j += 128) {
        int ia = j - PADL;       ia = ia < 0 ? 0 : (ia > 511 ? 511 : ia);
        int ib = j - (PADL - 1); ib = ib < 0 ? 0 : (ib > 511 ? 511 : ib);
        dst[j] = make_float2(sF[ia], sF[ib]);
    }
}

// ---------------- backprojection --------------------------------------------------------
// One block per (b, r, 16-row y-slab): 2048 blocks, 512 threads (one x column each).
__global__ void __launch_bounds__(512) bp_kernel(float* __restrict__ out) {
    __shared__ __align__(16) float2 srow[NPADE];
    __shared__ float2 scs[VV];

    int tid  = threadIdx.x;
    int blk  = blockIdx.x;
    int slab = blk & (NSLAB - 1);
    int img  = blk >> 5;         // NSLAB = 32
    int b    = img >> 5;         // RR = 32
    int r    = img & 31;

    if (tid < VV) scs[tid] = g_cs[tid];

    float xp    = (float)tid - 255.5f;
    float ybase = (float)(slab * YT) - 255.5f;
    float acc[YT];
    #pragma unroll
    for (int j = 0; j < YT; j++) acc[j] = 0.f;

    for (int v = 0; v < VV; v++) {
        __syncthreads();
        const float4* rp = g_fp4 + (size_t)((b * VV + v) * RR + r) * (NPADE / 2);
        if (tid < NPADE / 2) ((float4*)srow)[tid] = rp[tid];
        __syncthreads();

        float2 cs = scs[v];
        float t0 = fmaf(xp, cs.x, fmaf(ybase, cs.y, 255.5f + (float)PADL));
        #pragma unroll
        for (int j = 0; j < YT; j++) {
            float t = fmaf((float)j, cs.y, t0);   // independent per j (ILP)
            int i0 = (int)t;                      // t >= 0 -> trunc == floor
            float w = t - (float)i0;
            float2 g = srow[i0];                  // one LDS.64 -> both lerp taps
            acc[j] = fmaf(w, g.y - g.x, acc[j] + g.x);
        }
    }

    const float scale = (float)(PI_D / (double)VV);
    int y0 = slab * YT;
    size_t obase = (((size_t)(b * RR + r)) * NPIX + y0) * NPIX + tid;
    #pragma unroll
    for (int j = 0; j < YT; j++) {
        float val = acc[j] * scale;
        out[obase + (size_t)j * NPIX] = val > 0.f ? val : 0.f;
    }
}

// ---------------- launch ----------------------------------------------------------------
extern "C" void kernel_launch(void* const* d_in, const int* in_sizes, int n_in,
                              void* d_out, int out_size) {
    const float* sino = (const float*)d_in[0];
    float* out = (float*)d_out;
    (void)in_sizes; (void)n_in; (void)out_size;

    setup_kernel<<<513, 128>>>();
    filter_kernel<<<NROWS, 128>>>(sino);
    bp_kernel<<<BB * RR * NSLAB, 512>>>(out);
}

// round 4
// speedup vs baseline: 1.1089x; 1.1089x over previous
#include <cuda_runtime.h>
#include <math.h>

// Problem constants
#define BB 2
#define VV 180
#define RR 32
#define CC 512
#define NPIX 512
#define NROWS (BB*VV*RR)        // 11520
#define PADL 107
#define NPADE 724               // padded dup entries per row (covers floor(t)+PADL in [0,723])
#define YT 16
#define NSLAB (NPIX/YT)         // 32
#define PI_D 3.14159265358979323846

// ---------------- device globals (scratch; no runtime allocation allowed) ----------------
__device__ __align__(16) float  g_h[512];                    // ramp conv kernel
__device__ __align__(16) float2 g_cs[VV];                    // (cos, sin) per angle
__device__ __align__(16) float4 g_fp4[(size_t)NROWS * (NPADE/2)]; // padded (g0, d) rows, ~67MB

// ---------------- setup: h[j] = (1/512) sum_m ramp[m] cos(2 pi m j / 512); cs table -----
__global__ void setup_kernel() {
    __shared__ double part[128];
    int tid = threadIdx.x;
    if (blockIdx.x == 512) {
        for (int v = tid; v < VV; v += 128) {
            double th = PI_D * (double)v / (double)VV;
            g_cs[v] = make_float2((float)cos(th), (float)sin(th));
        }
        return;
    }
    int j = blockIdx.x;  // 0..511
    double s = 0.0;
    for (int m = tid; m < 512; m += 128) {
        double f = (m < 256) ? (double)m / 512.0 : (double)(m - 512) / 512.0;
        s += 2.0 * fabs(f) * cos(2.0 * PI_D * (double)m * (double)j / 512.0);
    }
    part[tid] = s;
    __syncthreads();
    for (int o = 64; o > 0; o >>= 1) {
        if (tid < o) part[tid] += part[tid + o];
        __syncthreads();
    }
    if (tid == 0) g_h[j] = (float)(part[0] / 512.0);
}

// ---------------- filter: circular conv + pad/(g0,d) write -----------------------------
// One block per sinogram row (11520 blocks), 128 threads, 4 consecutive outputs per thread.
__global__ void __launch_bounds__(128) filter_kernel(const float* __restrict__ sino) {
    __shared__ __align__(16) float srow2[1024];  // row duplicated (mod-512 window loads)
    __shared__ __align__(16) float sh[512];      // conv kernel
    __shared__ __align__(16) float sF[512];      // filtered output

    int row = blockIdx.x;
    int tid = threadIdx.x;

    const float4* rp = (const float4*)(sino + (size_t)row * CC);
    float4 rv4 = rp[tid];                               // 128 x float4 = 512 floats
    ((float4*)srow2)[tid]        = rv4;
    ((float4*)srow2)[tid + 128]  = rv4;                 // duplicate
    ((float4*)sh)[tid] = ((const float4*)g_h)[tid];
    __syncthreads();

    int c0 = tid * 4;
    float a0 = 0.f, a1 = 0.f, a2 = 0.f, a3 = 0.f;

    // F[c] = sum_d h[d] * row[(c-d) mod 512]
    #pragma unroll 4
    for (int d0 = 0; d0 < 512; d0 += 4) {
        float4 hv = *(const float4*)&sh[d0];            // broadcast across warp
        int base = c0 - d0 + 508;                       // 4-aligned, in [0,1016]
        float4 ra = *(const float4*)&srow2[base];       // offsets m=0..3
        float4 rb = *(const float4*)&srow2[base + 4];   // offsets m=4..7
        a0 = fmaf(hv.x, rb.x, a0); a0 = fmaf(hv.y, ra.w, a0); a0 = fmaf(hv.z, ra.z, a0); a0 = fmaf(hv.w, ra.y, a0);
        a1 = fmaf(hv.x, rb.y, a1); a1 = fmaf(hv.y, rb.x, a1); a1 = fmaf(hv.z, ra.w, a1); a1 = fmaf(hv.w, ra.z, a1);
        a2 = fmaf(hv.x, rb.z, a2); a2 = fmaf(hv.y, rb.y, a2); a2 = fmaf(hv.z, rb.x, a2); a2 = fmaf(hv.w, ra.w, a2);
        a3 = fmaf(hv.x, rb.w, a3); a3 = fmaf(hv.y, rb.z, a3); a3 = fmaf(hv.z, rb.y, a3); a3 = fmaf(hv.w, rb.x, a3);
    }
    *(float4*)&sF[c0] = make_float4(a0, a1, a2, a3);
    __syncthreads();

    // pad/dup: fp[j] = (g0, d) = (F[clamp(j-107)], F[clamp(j-106)] - F[clamp(j-107)])
    float2* dst = ((float2*)g_fp4) + (size_t)row * NPADE;
    for (int j = tid; j < NPADE; j += 128) {
        int ia = j - PADL;       ia = ia < 0 ? 0 : (ia > 511 ? 511 : ia);
        int ib = j - (PADL - 1); ib = ib < 0 ? 0 : (ib > 511 ? 511 : ib);
        float g0 = sF[ia];
        dst[j] = make_float2(g0, sF[ib] - g0);
    }
}

// ---------------- backprojection --------------------------------------------------------
// One block per (b, r, 16-row y-slab): 2048 blocks, 512 threads (one x column each).
// Double-buffered staging: prefetch angle v+1's padded row into registers while
// computing angle v; STS after the compute-side sync.
__global__ void __launch_bounds__(512, 2) bp_kernel(float* __restrict__ out) {
    __shared__ __align__(16) float2 srow[NPADE];
    __shared__ float2 scs[VV];

    int tid  = threadIdx.x;
    int blk  = blockIdx.x;
    int slab = blk & (NSLAB - 1);
    int img  = blk >> 5;         // NSLAB = 32
    int b    = img >> 5;         // RR = 32
    int r    = img & 31;

    if (tid < VV) scs[tid] = g_cs[tid];

    float xp    = (float)tid - 255.5f;
    float ybase = (float)(slab * YT) - 255.5f;
    float acc[YT];
    #pragma unroll
    for (int j = 0; j < YT; j++) acc[j] = 0.f;

    // row pointer for (b, *, r); v-stride in uint4 units
    const uint4* rowp = (const uint4*)(g_fp4 + (size_t)((b * VV) * RR + r) * (NPADE / 2));
    const size_t vstride = (size_t)RR * (NPADE * 8 / 16);   // uint4 per v step

    uint4 pre;
    bool loader = (tid < NPADE * 8 / 16);   // 362 threads stage 16B each
    if (loader) pre = rowp[tid];

    for (int v = 0; v < VV; v++) {
        if (loader) ((uint4*)srow)[tid] = pre;
        __syncthreads();
        if (v + 1 < VV && loader) pre = rowp[(size_t)(v + 1) * vstride + tid];  // overlaps compute

        float2 cs = scs[v];
        float t0 = fmaf(xp, cs.x, fmaf(ybase, cs.y, 255.5f + (float)PADL));
        #pragma unroll
        for (int j = 0; j < YT; j++) {
            float t = fmaf((float)j, cs.y, t0);   // independent per j (ILP)
            int i0 = (int)t;                      // t >= 0 -> trunc == floor
            float w = t - (float)i0;
            float2 g = srow[i0];                  // (g0, g1-g0): one LDS.64
            acc[j] = fmaf(w, g.y, acc[j] + g.x);
        }
        __syncthreads();
    }

    const float scale = (float)(PI_D / (double)VV);
    int y0 = slab * YT;
    size_t obase = (((size_t)(b * RR + r)) * NPIX + y0) * NPIX + tid;
    #pragma unroll
    for (int j = 0; j < YT; j++) {
        float val = acc[j] * scale;
        out[obase + (size_t)j * NPIX] = val > 0.f ? val : 0.f;
    }
}

// ---------------- launch ----------------------------------------------------------------
extern "C" void kernel_launch(void* const* d_in, const int* in_sizes, int n_in,
                              void* d_out, int out_size) {
    const float* sino = (const float*)d_in[0];
    float* out = (float*)d_out;
    (void)in_sizes; (void)n_in; (void)out_size;

    setup_kernel<<<513, 128>>>();
    filter_kernel<<<NROWS, 128>>>(sino);
    bp_kernel<<<BB * RR * NSLAB, 512>>>(out);
}

// round 5
// speedup vs baseline: 1.4002x; 1.2628x over previous
#include <cuda_runtime.h>
#include <cuda_fp16.h>
#include <math.h>

// Problem constants
#define BB 2
#define VV 180
#define RR 32
#define CC 512
#define NPIX 512
#define NROWS (BB*VV*RR)        // 11520
#define PADL 107
#define NPADE 724               // padded entries per row (floor(t) in [1,723])
#define RT 4                    // r-images per bp block
#define YTN 8                   // y rows per bp block
#define PI_D 3.14159265358979323846

// ---------------- device globals (scratch; no runtime allocation allowed) ----------------
__device__ __align__(16) float   g_h[512];                      // ramp conv kernel
__device__ __align__(16) float2  g_cs[VV];                      // (cos, sin) per angle
__device__ __align__(16) __half2 g_fph[(size_t)NROWS * NPADE];  // padded (g0, d) rows fp16, ~33MB

// ---------------- setup: h[j] = (1/512) sum_m ramp[m] cos(2 pi m j / 512); cs table -----
__global__ void setup_kernel() {
    __shared__ double part[128];
    int tid = threadIdx.x;
    if (blockIdx.x == 512) {
        for (int v = tid; v < VV; v += 128) {
            double th = PI_D * (double)v / (double)VV;
            g_cs[v] = make_float2((float)cos(th), (float)sin(th));
        }
        return;
    }
    int j = blockIdx.x;  // 0..511
    double s = 0.0;
    for (int m = tid; m < 512; m += 128) {
        double f = (m < 256) ? (double)m / 512.0 : (double)(m - 512) / 512.0;
        s += 2.0 * fabs(f) * cos(2.0 * PI_D * (double)m * (double)j / 512.0);
    }
    part[tid] = s;
    __syncthreads();
    for (int o = 64; o > 0; o >>= 1) {
        if (tid < o) part[tid] += part[tid + o];
        __syncthreads();
    }
    if (tid == 0) g_h[j] = (float)(part[0] / 512.0);
}

// ---------------- filter: circular conv + padded (g0,d) half2 write --------------------
// One block per sinogram row (11520 blocks), 128 threads, 4 consecutive outputs/thread.
__global__ void __launch_bounds__(128) filter_kernel(const float* __restrict__ sino) {
    __shared__ __align__(16) float srow2[1024];  // row duplicated (mod-512 window loads)
    __shared__ __align__(16) float sh[512];      // conv kernel
    __shared__ __align__(16) float sF[512];      // filtered output

    int row = blockIdx.x;
    int tid = threadIdx.x;

    const float4* rp = (const float4*)(sino + (size_t)row * CC);
    float4 rv4 = rp[tid];                               // 128 x float4 = 512 floats
    ((float4*)srow2)[tid]        = rv4;
    ((float4*)srow2)[tid + 128]  = rv4;                 // duplicate
    ((float4*)sh)[tid] = ((const float4*)g_h)[tid];
    __syncthreads();

    int c0 = tid * 4;
    float a0 = 0.f, a1 = 0.f, a2 = 0.f, a3 = 0.f;

    // F[c] = sum_d h[d] * row[(c-d) mod 512]
    #pragma unroll 4
    for (int d0 = 0; d0 < 512; d0 += 4) {
        float4 hv = *(const float4*)&sh[d0];            // broadcast across warp
        int base = c0 - d0 + 508;                       // 4-aligned, in [0,1016]
        float4 ra = *(const float4*)&srow2[base];
        float4 rb = *(const float4*)&srow2[base + 4];
        a0 = fmaf(hv.x, rb.x, a0); a0 = fmaf(hv.y, ra.w, a0); a0 = fmaf(hv.z, ra.z, a0); a0 = fmaf(hv.w, ra.y, a0);
        a1 = fmaf(hv.x, rb.y, a1); a1 = fmaf(hv.y, rb.x, a1); a1 = fmaf(hv.z, ra.w, a1); a1 = fmaf(hv.w, ra.z, a1);
        a2 = fmaf(hv.x, rb.z, a2); a2 = fmaf(hv.y, rb.y, a2); a2 = fmaf(hv.z, rb.x, a2); a2 = fmaf(hv.w, ra.w, a2);
        a3 = fmaf(hv.x, rb.w, a3); a3 = fmaf(hv.y, rb.z, a3); a3 = fmaf(hv.z, rb.y, a3); a3 = fmaf(hv.w, rb.x, a3);
    }
    *(float4*)&sF[c0] = make_float4(a0, a1, a2, a3);
    __syncthreads();

    // pad/dup: fph[j] = half2(g0, d) = (F[clamp(j-107)], F[clamp(j-106)] - F[clamp(j-107)])
    __half2* dst = g_fph + (size_t)row * NPADE;
    for (int j = tid; j < NPADE; j += 128) {
        int ia = j - PADL;       ia = ia < 0 ? 0 : (ia > 511 ? 511 : ia);
        int ib = j - (PADL - 1); ib = ib < 0 ? 0 : (ib > 511 ? 511 : ib);
        float g0 = sF[ia];
        dst[j] = __floats2half2_rn(g0, sF[ib] - g0);
    }
}

// ---------------- backprojection --------------------------------------------------------
// 1024 blocks: (b, 4-r group, 8-y slab) x 512 threads (one x each).
// Index math (t, i0, w) shared across the 4 r-images; half2 (g0,d) gather = LDS.32.
// Double-buffered smem: 1 sync per angle; STS(v+1) + LDG(v+2) overlap compute(v).
#define CHUNK4 (RT * NPADE / 4)       // uint4 per staged chunk = 724
__global__ void __launch_bounds__(512, 2) bp_kernel(float* __restrict__ out) {
    __shared__ __align__(16) __half2 sbuf[2][RT * NPADE];
    __shared__ float2 scs[VV];

    int tid  = threadIdx.x;
    int blk  = blockIdx.x;
    int slab = blk & 63;              // NPIX/YTN = 64
    int rg   = (blk >> 6) & 7;        // RR/RT = 8
    int b    = blk >> 9;

    if (tid < VV) scs[tid] = g_cs[tid];

    // contiguous chunk of RT rows: (b, v, rg*RT .. rg*RT+3)
    const uint4* basep = (const uint4*)(g_fph + ((size_t)(b * VV) * RR + rg * RT) * NPADE);
    const size_t vstr  = (size_t)RR * NPADE / 4;   // uint4 per v step

    bool l2 = tid < (CHUNK4 - 512);   // 212 threads load a second uint4
    uint4 p0 = basep[tid];
    uint4 p1; if (l2) p1 = basep[tid + 512];
    ((uint4*)sbuf[0])[tid] = p0;
    if (l2) ((uint4*)sbuf[0])[tid + 512] = p1;
    p0 = basep[vstr + tid];
    if (l2) p1 = basep[vstr + tid + 512];
    __syncthreads();

    float xp = (float)tid - 255.5f;
    float yb = (float)(slab * YTN) - 255.5f;
    float acc[RT][YTN];
    #pragma unroll
    for (int rr = 0; rr < RT; rr++)
        #pragma unroll
        for (int j = 0; j < YTN; j++) acc[rr][j] = 0.f;

    for (int v = 0; v < VV; v++) {
        if (v + 1 < VV) {   // store prefetched v+1 into the other buffer
            uint4* nb = (uint4*)sbuf[(v + 1) & 1];
            nb[tid] = p0;
            if (l2) nb[tid + 512] = p1;
        }
        const __half2* cur = sbuf[v & 1];
        float2 cs = scs[v];
        float t0 = fmaf(xp, cs.x, fmaf(yb, cs.y, 255.5f + (float)PADL));
        #pragma unroll
        for (int j = 0; j < YTN; j++) {
            float t = fmaf((float)j, cs.y, t0);
            int i0 = (int)t;                       // t >= 1 -> trunc == floor
            float w = t - (float)i0;
            #pragma unroll
            for (int rr = 0; rr < RT; rr++) {
                float2 g = __half22float2(cur[rr * NPADE + i0]);  // (g0, g1-g0)
                acc[rr][j] = fmaf(w, g.y, acc[rr][j] + g.x);
            }
        }
        if (v + 2 < VV) {   // prefetch v+2 (overlaps next iteration's compute)
            p0 = basep[(size_t)(v + 2) * vstr + tid];
            if (l2) p1 = basep[(size_t)(v + 2) * vstr + tid + 512];
        }
        __syncthreads();
    }

    const float scale = (float)(PI_D / (double)VV);
    int y0 = slab * YTN;
    #pragma unroll
    for (int rr = 0; rr < RT; rr++) {
        size_t obase = (((size_t)(b * RR + rg * RT + rr)) * NPIX + y0) * NPIX + tid;
        #pragma unroll
        for (int j = 0; j < YTN; j++) {
            float val = acc[rr][j] * scale;
            out[obase + (size_t)j * NPIX] = val > 0.f ? val : 0.f;
        }
    }
}

// ---------------- launch ----------------------------------------------------------------
extern "C" void kernel_launch(void* const* d_in, const int* in_sizes, int n_in,
                              void* d_out, int out_size) {
    const float* sino = (const float*)d_in[0];
    float* out = (float*)d_out;
    (void)in_sizes; (void)n_in; (void)out_size;

    setup_kernel<<<513, 128>>>();
    filter_kernel<<<NROWS, 128>>>(sino);
    bp_kernel<<<BB * (RR / RT) * (NPIX / YTN), 512>>>(out);
}

// round 6
// speedup vs baseline: 1.6742x; 1.1956x over previous
#include <cuda_runtime.h>
#include <cuda_fp16.h>
#include <math.h>

// Problem constants
#define BB 2
#define VV 180
#define RR 32
#define CC 512
#define NPIX 512
#define NROWS (BB*VV*RR)        // 11520
#define NPAIRS (NROWS/2)        // 5760
#define PADL 107
#define NPADE 724               // padded entries per row (floor(t) in [1,723])
#define RT 4                    // r-images per bp block (2 pairs)
#define YTN 8                   // y rows per bp block
#define PI_D 3.14159265358979323846

// ---------------- device globals (scratch; no runtime allocation allowed) ----------------
__device__ __align__(16) float  g_h[512];                       // ramp conv kernel
__device__ __align__(16) float2 g_cs[VV];                       // (cos, sin) per angle
// pair-interleaved padded rows: entry = (half2(g0_A,g0_B), half2(d_A,d_B)), ~33MB
__device__ __align__(16) uint2  g_pair[(size_t)NPAIRS * NPADE];

// ---------------- setup: h[j] = (1/512) sum_m ramp[m] cos(2 pi m j / 512); cs table -----
__global__ void setup_kernel() {
    __shared__ double part[128];
    int tid = threadIdx.x;
    if (blockIdx.x == 512) {
        for (int v = tid; v < VV; v += 128) {
            double th = PI_D * (double)v / (double)VV;
            g_cs[v] = make_float2((float)cos(th), (float)sin(th));
        }
        return;
    }
    int j = blockIdx.x;  // 0..511
    double s = 0.0;
    for (int m = tid; m < 512; m += 128) {
        double f = (m < 256) ? (double)m / 512.0 : (double)(m - 512) / 512.0;
        s += 2.0 * fabs(f) * cos(2.0 * PI_D * (double)m * (double)j / 512.0);
    }
    part[tid] = s;
    __syncthreads();
    for (int o = 64; o > 0; o >>= 1) {
        if (tid < o) part[tid] += part[tid + o];
        __syncthreads();
    }
    if (tid == 0) g_h[j] = (float)(part[0] / 512.0);
}

// ---------------- filter: 2 rows/block, circular conv (sliding reuse) + pair write -----
// 5760 blocks x 256 threads; group g = row within pair, 128 threads per row,
// 4 consecutive outputs per thread. rb(d0+4)==ra(d0) -> 1 data LDS.128 per step.
__global__ void __launch_bounds__(256) filter_kernel(const float* __restrict__ sino) {
    __shared__ __align__(16) float srow2[2][1024];  // each row duplicated (mod-512 windows)
    __shared__ __align__(16) float sh[512];         // conv kernel
    __shared__ __align__(16) float sF[2][512];      // filtered outputs

    int pairblk = blockIdx.x;          // 0..5759
    int g   = threadIdx.x >> 7;        // 0/1 : row within pair
    int tid = threadIdx.x & 127;

    const float4* rp = (const float4*)(sino + (size_t)(pairblk * 2 + g) * CC);
    float4 rv4 = rp[tid];
    ((float4*)srow2[g])[tid]       = rv4;
    ((float4*)srow2[g])[tid + 128] = rv4;           // duplicate
    if (g == 0) ((float4*)sh)[tid] = ((const float4*)g_h)[tid];
    __syncthreads();

    const float* rw = srow2[g];
    int c0 = tid * 4;
    float a0 = 0.f, a1 = 0.f, a2 = 0.f, a3 = 0.f;

    float4 rb = *(const float4*)&rw[c0 + 512];      // rb for d0=0
    #pragma unroll 4
    for (int d0 = 0; d0 < 512; d0 += 4) {
        float4 hv = *(const float4*)&sh[d0];        // warp-broadcast
        float4 ra = *(const float4*)&rw[c0 - d0 + 508];
        a0 = fmaf(hv.x, rb.x, a0); a0 = fmaf(hv.y, ra.w, a0); a0 = fmaf(hv.z, ra.z, a0); a0 = fmaf(hv.w, ra.y, a0);
        a1 = fmaf(hv.x, rb.y, a1); a1 = fmaf(hv.y, rb.x, a1); a1 = fmaf(hv.z, ra.w, a1); a1 = fmaf(hv.w, ra.z, a1);
        a2 = fmaf(hv.x, rb.z, a2); a2 = fmaf(hv.y, rb.y, a2); a2 = fmaf(hv.z, rb.x, a2); a2 = fmaf(hv.w, ra.w, a2);
        a3 = fmaf(hv.x, rb.w, a3); a3 = fmaf(hv.y, rb.z, a3); a3 = fmaf(hv.z, rb.y, a3); a3 = fmaf(hv.w, rb.x, a3);
        rb = ra;                                    // sliding-window reuse
    }
    *(float4*)&sF[g][c0] = make_float4(a0, a1, a2, a3);
    __syncthreads();

    // pair write: entry[j] = (half2(g0_A, g0_B), half2(d_A, d_B))
    uint2* dst = g_pair + (size_t)pairblk * NPADE;
    for (int j = threadIdx.x; j < NPADE; j += 256) {
        int ia = j - PADL;       ia = ia < 0 ? 0 : (ia > 511 ? 511 : ia);
        int ib = j - (PADL - 1); ib = ib < 0 ? 0 : (ib > 511 ? 511 : ib);
        float g0A = sF[0][ia], dA = sF[0][ib] - g0A;
        float g0B = sF[1][ia], dB = sF[1][ib] - g0B;
        __half2 lo = __floats2half2_rn(g0A, g0B);
        __half2 hi = __floats2half2_rn(dA, dB);
        uint2 e;
        e.x = *(unsigned int*)&lo;
        e.y = *(unsigned int*)&hi;
        dst[j] = e;
    }
}

// ---------------- backprojection --------------------------------------------------------
// 1024 blocks: (b, 4-r group = 2 pairs, 8-y slab) x 512 threads (one x each).
// HFMA2 pair-lerp: one LDS.64 + one HFMA2 covers 2 r-samples.
// Double-buffered smem: 1 sync per angle; STS(v+1) + LDG(v+2) overlap compute(v).
#define CHUNK4 (2 * NPADE * 8 / 16)    // uint4 per staged 2-pair chunk = 724
__global__ void __launch_bounds__(512, 2) bp_kernel(float* __restrict__ out) {
    __shared__ __align__(16) uint2 sbuf[2][2 * NPADE];  // [buf][pair*NPADE + j]
    __shared__ float2 scs[VV];

    int tid  = threadIdx.x;
    int blk  = blockIdx.x;
    int slab = blk & 63;              // NPIX/YTN = 64
    int rg   = (blk >> 6) & 7;        // RR/RT = 8
    int b    = blk >> 9;

    if (tid < VV) scs[tid] = g_cs[tid];

    // contiguous chunk of 2 pairs: (b, v, pairs rg*2, rg*2+1)
    const uint4* basep = (const uint4*)(g_pair + ((size_t)(b * VV) * (RR / 2) + rg * 2) * NPADE);
    const size_t vstr  = (size_t)(RR / 2) * NPADE / 2;   // uint4 per v step

    bool l2 = tid < (CHUNK4 - 512);   // 212 threads load a second uint4
    uint4 p0 = basep[tid];
    uint4 p1; if (l2) p1 = basep[tid + 512];
    ((uint4*)sbuf[0])[tid] = p0;
    if (l2) ((uint4*)sbuf[0])[tid + 512] = p1;
    p0 = basep[vstr + tid];
    if (l2) p1 = basep[vstr + tid + 512];
    __syncthreads();

    float xp = (float)tid - 255.5f;
    float yb = (float)(slab * YTN) - 255.5f;
    float acc[RT][YTN];
    #pragma unroll
    for (int rr = 0; rr < RT; rr++)
        #pragma unroll
        for (int j = 0; j < YTN; j++) acc[rr][j] = 0.f;

    for (int v = 0; v < VV; v++) {
        if (v + 1 < VV) {   // store prefetched v+1 into the other buffer
            uint4* nb = (uint4*)sbuf[(v + 1) & 1];
            nb[tid] = p0;
            if (l2) nb[tid + 512] = p1;
        }
        const uint2* cur = sbuf[v & 1];
        float2 cs = scs[v];
        float t0 = fmaf(xp, cs.x, fmaf(yb, cs.y, 255.5f + (float)PADL));
        #pragma unroll
        for (int j = 0; j < YTN; j++) {
            float t = fmaf((float)j, cs.y, t0);
            int i0 = (int)t;                       // t >= 1 -> trunc == floor
            float w = t - (float)i0;
            __half2 w2 = __float2half2_rn(w);
            #pragma unroll
            for (int pp = 0; pp < 2; pp++) {
                uint2 e = cur[pp * NPADE + i0];    // LDS.64: (g0A,g0B | dA,dB)
                __half2 val = __hfma2(w2, *(__half2*)&e.y, *(__half2*)&e.x);
                acc[pp * 2 + 0][j] += __low2float(val);
                acc[pp * 2 + 1][j] += __high2float(val);
            }
        }
        if (v + 2 < VV) {   // prefetch v+2 (overlaps next iteration's compute)
            p0 = basep[(size_t)(v + 2) * vstr + tid];
            if (l2) p1 = basep[(size_t)(v + 2) * vstr + tid + 512];
        }
        __syncthreads();
    }

    const float scale = (float)(PI_D / (double)VV);
    int y0 = slab * YTN;
    #pragma unroll
    for (int rr = 0; rr < RT; rr++) {
        size_t obase = (((size_t)(b * RR + rg * RT + rr)) * NPIX + y0) * NPIX + tid;
        #pragma unroll
        for (int j = 0; j < YTN; j++) {
            float val = acc[rr][j] * scale;
            out[obase + (size_t)j * NPIX] = val > 0.f ? val : 0.f;
        }
    }
}

// ---------------- launch ----------------------------------------------------------------
extern "C" void kernel_launch(void* const* d_in, const int* in_sizes, int n_in,
                              void* d_out, int out_size) {
    const float* sino = (const float*)d_in[0];
    float* out = (float*)d_out;
    (void)in_sizes; (void)n_in; (void)out_size;

    setup_kernel<<<513, 128>>>();
    filter_kernel<<<NPAIRS, 256>>>(sino);
    bp_kernel<<<BB * (RR / RT) * (NPIX / YTN), 512>>>(out);
}